// round 3
// baseline (speedup 1.0000x reference)
#include <cuda_runtime.h>
#include <math.h>

#define SEQ   16384
#define HID   1152
#define HEADS 16
#define HD    72
#define INTER 4304
#define NWIN  256
#define WIN   64

// ---------------------------------------------------------------------------
// Scratch (device globals; no runtime allocation allowed)
// ---------------------------------------------------------------------------
__device__ float g_h   [(size_t)SEQ * HID];        // LN1 / LN2 output
__device__ float g_qkv [(size_t)SEQ * 3 * HID];    // qkv projection (RoPE in-place)
__device__ float g_attn[(size_t)SEQ * HID];        // attention output
__device__ float g_x1  [(size_t)SEQ * HID];        // post-attention residual
__device__ float g_m   [(size_t)SEQ * INTER];      // fc1+gelu output

// ---------------------------------------------------------------------------
// LayerNorm: one warp per row (HID = 1152 = 32 * 36)
// ---------------------------------------------------------------------------
__global__ void ln_kernel(const float* __restrict__ in,
                          const float* __restrict__ w,
                          const float* __restrict__ b,
                          float* __restrict__ out)
{
    int warp = (blockIdx.x * blockDim.x + threadIdx.x) >> 5;
    int lane = threadIdx.x & 31;
    if (warp >= SEQ) return;

    const float* row = in + (size_t)warp * HID;
    float v[36];
    float s = 0.f, s2 = 0.f;
#pragma unroll
    for (int i = 0; i < 36; i++) {
        v[i] = row[lane + 32 * i];
        s  += v[i];
        s2 += v[i] * v[i];
    }
#pragma unroll
    for (int o = 16; o > 0; o >>= 1) {
        s  += __shfl_xor_sync(0xFFFFFFFFu, s,  o);
        s2 += __shfl_xor_sync(0xFFFFFFFFu, s2, o);
    }
    float mean = s * (1.0f / HID);
    float var  = s2 * (1.0f / HID) - mean * mean;
    float rstd = rsqrtf(var + 1e-6f);

    float* orow = out + (size_t)warp * HID;
#pragma unroll
    for (int i = 0; i < 36; i++) {
        int c = lane + 32 * i;
        orow[c] = (v[i] - mean) * rstd * w[c] + b[c];
    }
}

// ---------------------------------------------------------------------------
// Tiled fp32 GEMM: C[M,N] = A[M,K] @ B[K,N] + bias (+ resid / gelu per EPI)
// BM=BN=128, BK=8, 256 threads, 8x8 per thread.
// M % 128 == 0, K % 8 == 0, N % 4 == 0 always hold for this problem.
// EPI: 0 = bias, 1 = bias + residual, 2 = bias + gelu(tanh)
// ---------------------------------------------------------------------------
template <int EPI>
__global__ __launch_bounds__(256) void gemm_kernel(
    const float* __restrict__ A, const float* __restrict__ B,
    const float* __restrict__ bias, const float* __restrict__ resid,
    float* __restrict__ C, int M, int N, int K)
{
    __shared__ __align__(16) float As[8][128];
    __shared__ __align__(16) float Bs[8][128];

    int tid = threadIdx.x;
    int tx = tid & 15;          // 0..15 -> N direction
    int ty = tid >> 4;          // 0..15 -> M direction
    int rowBase = blockIdx.y * 128;
    int colBase = blockIdx.x * 128;

    float acc[8][8] = {};

    // A tile load: thread -> (row, 4-float chunk)
    int arow  = tid >> 1;
    int apart = (tid & 1) * 4;
    const float* Aptr = A + (size_t)(rowBase + arow) * K + apart;

    // B tile load: thread -> (k-row, 4-float chunk of columns)
    int brow = tid >> 5;
    int bcol = (tid & 31) * 4;
    int gcol = colBase + bcol;
    bool bvalid = (gcol < N);
    const float* Bptr = B + (size_t)brow * N + gcol;

    for (int k0 = 0; k0 < K; k0 += 8) {
        float4 a4 = *(const float4*)(Aptr + k0);
        As[apart + 0][arow] = a4.x;
        As[apart + 1][arow] = a4.y;
        As[apart + 2][arow] = a4.z;
        As[apart + 3][arow] = a4.w;

        float4 b4 = bvalid ? *(const float4*)(Bptr + (size_t)k0 * N)
                           : make_float4(0.f, 0.f, 0.f, 0.f);
        *(float4*)&Bs[brow][bcol] = b4;

        __syncthreads();

#pragma unroll
        for (int k = 0; k < 8; k++) {
            float a[8], bb[8];
#pragma unroll
            for (int i = 0; i < 8; i++) a[i]  = As[k][ty * 8 + i];
#pragma unroll
            for (int j = 0; j < 8; j++) bb[j] = Bs[k][tx * 8 + j];
#pragma unroll
            for (int i = 0; i < 8; i++)
#pragma unroll
                for (int j = 0; j < 8; j++)
                    acc[i][j] += a[i] * bb[j];
        }
        __syncthreads();
    }

#pragma unroll
    for (int i = 0; i < 8; i++) {
        int row = rowBase + ty * 8 + i;
#pragma unroll
        for (int j = 0; j < 8; j++) {
            int col = colBase + tx * 8 + j;
            if (col < N) {
                float v = acc[i][j] + bias[col];
                if (EPI == 1) v += resid[(size_t)row * N + col];
                if (EPI == 2) {
                    float u = v;
                    float t = 0.7978845608028654f * (u + 0.044715f * u * u * u);
                    v = 0.5f * u * (1.f + tanhf(t));
                }
                C[(size_t)row * N + col] = v;
            }
        }
    }
}

// ---------------------------------------------------------------------------
// RoPE applied in place on q and k slices of g_qkv.
// One thread per (token, part in {q,k}, head, d < 36) rotation pair.
// ---------------------------------------------------------------------------
__global__ void rope_kernel(float* __restrict__ qkv,
                            const float* __restrict__ cosb,
                            const float* __restrict__ sinb)
{
    int idx = blockIdx.x * blockDim.x + threadIdx.x;
    const int total = SEQ * 2 * HEADS * 36;
    if (idx >= total) return;

    int d = idx % 36;   int t = idx / 36;
    int h = t % HEADS;  t /= HEADS;
    int part = t & 1;   int s = t >> 1;

    float c0  = cosb[s * HD + d];
    float sn0 = sinb[s * HD + d];
    float c1  = cosb[s * HD + d + 36];
    float sn1 = sinb[s * HD + d + 36];

    size_t base = (size_t)s * (3 * HID) + part * HID + h * HD;
    float v0 = qkv[base + d];
    float v1 = qkv[base + d + 36];
    qkv[base + d]      = v0 * c0 - v1 * sn0;   // q*cos + (-t2)*sin
    qkv[base + d + 36] = v1 * c1 + v0 * sn1;   // q*cos + ( t1)*sin
}

// ---------------------------------------------------------------------------
// Windowed attention: one block per (window, head). 128 threads.
// q,k,v tiles (64x72, padded to 73) + score matrix (64x65) in dynamic smem.
// ---------------------------------------------------------------------------
__global__ __launch_bounds__(128) void attn_kernel(const float* __restrict__ qkv,
                                                   float* __restrict__ out)
{
    extern __shared__ float sm[];
    float* sq = sm;                 // 64*73
    float* sk = sq + 64 * 73;       // 64*73
    float* sv = sk + 64 * 73;       // 64*73
    float* ss = sv + 64 * 73;       // 64*65

    int w   = blockIdx.x >> 4;
    int h   = blockIdx.x & 15;
    int tid = threadIdx.x;

    for (int i = tid; i < 64 * 72; i += 128) {
        int r = i / 72, d = i % 72;
        size_t base = (size_t)(w * 64 + r) * (3 * HID) + h * HD + d;
        sq[r * 73 + d] = qkv[base];
        sk[r * 73 + d] = qkv[base + HID];
        sv[r * 73 + d] = qkv[base + 2 * HID];
    }
    __syncthreads();

    const float scale = 0.11785113019775793f;   // 72^-0.5
    int r    = tid >> 1;
    int half = tid & 1;

    // scores: thread covers row r, half the key range
    for (int j = half * 32; j < half * 32 + 32; j++) {
        float a = 0.f;
#pragma unroll
        for (int d = 0; d < 72; d++) a += sq[r * 73 + d] * sk[j * 73 + d];
        ss[r * 65 + j] = a * scale;
    }
    __syncthreads();

    // softmax per row (first 64 threads)
    if (tid < 64) {
        float mx = -1e30f;
        for (int j = 0; j < 64; j++) mx = fmaxf(mx, ss[tid * 65 + j]);
        float sum = 0.f;
        for (int j = 0; j < 64; j++) {
            float e = __expf(ss[tid * 65 + j] - mx);
            ss[tid * 65 + j] = e;
            sum += e;
        }
        float inv = 1.f / sum;
        for (int j = 0; j < 64; j++) ss[tid * 65 + j] *= inv;
    }
    __syncthreads();

    // probs @ V: thread covers row r, half the head-dim
    {
        int dbase = half * 36;
        float acc[36] = {};
        for (int j = 0; j < 64; j++) {
            float p = ss[r * 65 + j];
#pragma unroll
            for (int d = 0; d < 36; d++) acc[d] += p * sv[j * 73 + dbase + d];
        }
        size_t obase = (size_t)(w * 64 + r) * HID + h * HD + dbase;
#pragma unroll
        for (int d = 0; d < 36; d++) out[obase + d] = acc[d];
    }
}

// ---------------------------------------------------------------------------
// Launch
// ---------------------------------------------------------------------------
extern "C" void kernel_launch(void* const* d_in, const int* in_sizes, int n_in,
                              void* d_out, int out_size)
{
    const float* x      = (const float*)d_in[0];
    const float* cosb   = (const float*)d_in[1];
    const float* sinb   = (const float*)d_in[2];
    // d_in[3] = cu_seqlens (int32) — windows are uniform WIN=64, unused
    const float* qkv_w  = (const float*)d_in[4];
    const float* qkv_b  = (const float*)d_in[5];
    const float* proj_w = (const float*)d_in[6];
    const float* proj_b = (const float*)d_in[7];
    const float* ln1_w  = (const float*)d_in[8];
    const float* ln1_b  = (const float*)d_in[9];
    const float* ln2_w  = (const float*)d_in[10];
    const float* ln2_b  = (const float*)d_in[11];
    const float* fc1_w  = (const float*)d_in[12];
    const float* fc1_b  = (const float*)d_in[13];
    const float* fc2_w  = (const float*)d_in[14];
    const float* fc2_b  = (const float*)d_in[15];
    float* out = (float*)d_out;

    float *ph, *pqkv, *pattn, *px1, *pm;
    cudaGetSymbolAddress((void**)&ph,    g_h);
    cudaGetSymbolAddress((void**)&pqkv,  g_qkv);
    cudaGetSymbolAddress((void**)&pattn, g_attn);
    cudaGetSymbolAddress((void**)&px1,   g_x1);
    cudaGetSymbolAddress((void**)&pm,    g_m);

    const int ATTN_SMEM = (64 * 73 * 3 + 64 * 65) * 4;   // 72704 bytes
    cudaFuncSetAttribute(attn_kernel,
                         cudaFuncAttributeMaxDynamicSharedMemorySize, ATTN_SMEM);

    // 1) LN1(x) -> h
    ln_kernel<<<SEQ / 8, 256>>>(x, ln1_w, ln1_b, ph);

    // 2) qkv = h @ qkv_w + qkv_b      [16384,1152]x[1152,3456]
    gemm_kernel<0><<<dim3(3 * HID / 128, SEQ / 128), 256>>>(
        ph, qkv_w, qkv_b, nullptr, pqkv, SEQ, 3 * HID, HID);

    // 3) RoPE in place on q, k
    {
        int n = SEQ * 2 * HEADS * 36;
        rope_kernel<<<(n + 255) / 256, 256>>>(pqkv, cosb, sinb);
    }

    // 4) windowed attention
    attn_kernel<<<NWIN * HEADS, 128, ATTN_SMEM>>>(pqkv, pattn);

    // 5) x1 = x + attn @ proj_w + proj_b
    gemm_kernel<1><<<dim3(HID / 128, SEQ / 128), 256>>>(
        pattn, proj_w, proj_b, x, px1, SEQ, HID, HID);

    // 6) LN2(x1) -> h
    ln_kernel<<<SEQ / 8, 256>>>(px1, ln2_w, ln2_b, ph);

    // 7) m = gelu(h @ fc1_w + fc1_b)   N=4304 (needs guard)
    gemm_kernel<2><<<dim3((INTER + 127) / 128, SEQ / 128), 256>>>(
        ph, fc1_w, fc1_b, nullptr, pm, SEQ, INTER, HID);

    // 8) out = x1 + m @ fc2_w + fc2_b
    gemm_kernel<1><<<dim3(HID / 128, SEQ / 128), 256>>>(
        pm, fc2_w, fc2_b, px1, out, SEQ, HID, INTER);
}

// round 6
// speedup vs baseline: 3.0841x; 3.0841x over previous
#include <cuda_runtime.h>
#include <math.h>
#include <stdint.h>

#define SEQ   16384
#define HID   1152
#define HEADS 16
#define HD    72
#define INTER 4304
#define NWIN  256

// ---------------------------------------------------------------------------
// Scratch (device globals; no runtime allocation allowed)
// ---------------------------------------------------------------------------
__device__ float g_h   [(size_t)SEQ * HID];
__device__ float g_qkv [(size_t)SEQ * 3 * HID];
__device__ float g_attn[(size_t)SEQ * HID];
__device__ float g_x1  [(size_t)SEQ * HID];
__device__ float g_m   [(size_t)SEQ * INTER];

// ---------------------------------------------------------------------------
// LayerNorm: one warp per row (HID = 1152 = 32 * 36)
// ---------------------------------------------------------------------------
__global__ void ln_kernel(const float* __restrict__ in,
                          const float* __restrict__ w,
                          const float* __restrict__ b,
                          float* __restrict__ out)
{
    int warp = (blockIdx.x * blockDim.x + threadIdx.x) >> 5;
    int lane = threadIdx.x & 31;
    if (warp >= SEQ) return;

    const float* row = in + (size_t)warp * HID;
    float v[36];
    float s = 0.f, s2 = 0.f;
#pragma unroll
    for (int i = 0; i < 36; i++) {
        v[i] = row[lane + 32 * i];
        s  += v[i];
        s2 += v[i] * v[i];
    }
#pragma unroll
    for (int o = 16; o > 0; o >>= 1) {
        s  += __shfl_xor_sync(0xFFFFFFFFu, s,  o);
        s2 += __shfl_xor_sync(0xFFFFFFFFu, s2, o);
    }
    float mean = s * (1.0f / HID);
    float var  = s2 * (1.0f / HID) - mean * mean;
    float rstd = rsqrtf(var + 1e-6f);

    float* orow = out + (size_t)warp * HID;
#pragma unroll
    for (int i = 0; i < 36; i++) {
        int c = lane + 32 * i;
        orow[c] = (v[i] - mean) * rstd * w[c] + b[c];
    }
}

// ---------------------------------------------------------------------------
// tf32 tensor-core GEMM: C[M,N] = A[M,K] @ B[K,N] + bias (+resid / gelu)
// 128x128x32 CTA tile, 256 threads (2x4 warps, 64x32 per warp),
// double-buffered cp.async, mma.sync.m16n8k8.tf32.
// EPI: 0 = bias, 1 = bias + residual, 2 = bias + gelu(tanh)
// ---------------------------------------------------------------------------
#define BM 128
#define BN 128
#define BK 32
#define ASTRIDE 36     // 128x(32+4)  -> bank (4g+t), conflict-free, 16B aligned
#define BSTRIDE 136    // 32x(128+8)  -> bank (8t+g), conflict-free, 16B aligned
#define A_TILE (BM * ASTRIDE)   // 4608 floats
#define B_TILE (BK * BSTRIDE)   // 4352 floats
#define GEMM_SMEM ((2 * A_TILE + 2 * B_TILE) * 4)   // 71680 bytes

__device__ __forceinline__ uint32_t f2tf32(float f)
{
    uint32_t u;
    asm("cvt.rna.tf32.f32 %0, %1;" : "=r"(u) : "f"(f));
    return u;
}

template <int EPI>
__global__ __launch_bounds__(256) void gemm_tf32(
    const float* __restrict__ A, const float* __restrict__ B,
    const float* __restrict__ bias, const float* __restrict__ resid,
    float* __restrict__ C, int M, int N, int K)
{
    extern __shared__ float smf[];
    float* sA = smf;                  // [2][128][36]
    float* sB = smf + 2 * A_TILE;     // [2][32][136]

    const int tid  = threadIdx.x;
    const int lane = tid & 31, warp = tid >> 5;
    const int g = lane >> 2, t = lane & 3;
    const int wm = (warp >> 2) * 64, wn = (warp & 3) * 32;
    const int rowBase = blockIdx.y * BM, colBase = blockIdx.x * BN;

    float acc[4][4][4];
#pragma unroll
    for (int i = 0; i < 4; i++)
#pragma unroll
        for (int j = 0; j < 4; j++)
#pragma unroll
            for (int c = 0; c < 4; c++) acc[i][j][c] = 0.f;

    const int nkt = (K + BK - 1) / BK;

    auto loadA = [&](int stage, int k0) {
#pragma unroll
        for (int i = 0; i < 4; i++) {
            int c  = tid + i * 256;
            int m  = c >> 3;
            int kc = (c & 7) * 4;
            int gk = k0 + kc;
            int sz = (gk < K) ? 16 : 0;
            const float* src = A + (size_t)(rowBase + m) * K + min(gk, K - 4);
            uint32_t dst = (uint32_t)__cvta_generic_to_shared(
                sA + stage * A_TILE + m * ASTRIDE + kc);
            asm volatile("cp.async.cg.shared.global [%0], [%1], 16, %2;\n"
                         :: "r"(dst), "l"(src), "r"(sz));
        }
    };
    auto loadB = [&](int stage, int k0) {
#pragma unroll
        for (int i = 0; i < 4; i++) {
            int c  = tid + i * 256;
            int kr = c >> 5;
            int nc = (c & 31) * 4;
            int gk = k0 + kr;
            int gn = colBase + nc;
            int sz = (gk < K && gn < N) ? 16 : 0;
            const float* src = B + (size_t)min(gk, K - 1) * N + min(gn, N - 4);
            uint32_t dst = (uint32_t)__cvta_generic_to_shared(
                sB + stage * B_TILE + kr * BSTRIDE + nc);
            asm volatile("cp.async.cg.shared.global [%0], [%1], 16, %2;\n"
                         :: "r"(dst), "l"(src), "r"(sz));
        }
    };

    loadA(0, 0);
    loadB(0, 0);
    asm volatile("cp.async.commit_group;\n");

    int stage = 0;
    for (int kt = 0; kt < nkt; kt++) {
        if (kt + 1 < nkt) {
            loadA(stage ^ 1, (kt + 1) * BK);
            loadB(stage ^ 1, (kt + 1) * BK);
            asm volatile("cp.async.commit_group;\n");
            asm volatile("cp.async.wait_group 1;\n");
        } else {
            asm volatile("cp.async.wait_group 0;\n");
        }
        __syncthreads();

        const float* a_s = sA + stage * A_TILE;
        const float* b_s = sB + stage * B_TILE;

#pragma unroll
        for (int ks = 0; ks < 4; ks++) {
            const int k8 = ks * 8;
            uint32_t af[4][4], bf[4][2];
#pragma unroll
            for (int mt = 0; mt < 4; mt++) {
                int r = wm + mt * 16 + g;
                af[mt][0] = f2tf32(a_s[(r    ) * ASTRIDE + k8 + t    ]);
                af[mt][1] = f2tf32(a_s[(r + 8) * ASTRIDE + k8 + t    ]);
                af[mt][2] = f2tf32(a_s[(r    ) * ASTRIDE + k8 + t + 4]);
                af[mt][3] = f2tf32(a_s[(r + 8) * ASTRIDE + k8 + t + 4]);
            }
#pragma unroll
            for (int nt = 0; nt < 4; nt++) {
                int cc = wn + nt * 8 + g;
                bf[nt][0] = f2tf32(b_s[(k8 + t    ) * BSTRIDE + cc]);
                bf[nt][1] = f2tf32(b_s[(k8 + t + 4) * BSTRIDE + cc]);
            }
#pragma unroll
            for (int mt = 0; mt < 4; mt++)
#pragma unroll
                for (int nt = 0; nt < 4; nt++) {
                    asm volatile(
                        "mma.sync.aligned.m16n8k8.row.col.f32.tf32.tf32.f32 "
                        "{%0,%1,%2,%3}, {%4,%5,%6,%7}, {%8,%9}, {%0,%1,%2,%3};\n"
                        : "+f"(acc[mt][nt][0]), "+f"(acc[mt][nt][1]),
                          "+f"(acc[mt][nt][2]), "+f"(acc[mt][nt][3])
                        : "r"(af[mt][0]), "r"(af[mt][1]),
                          "r"(af[mt][2]), "r"(af[mt][3]),
                          "r"(bf[nt][0]), "r"(bf[nt][1]));
                }
        }
        __syncthreads();
        stage ^= 1;
    }

    // Epilogue: c0,c1 at (row=g, cols 2t,2t+1); c2,c3 at row g+8.
#pragma unroll
    for (int mt = 0; mt < 4; mt++) {
#pragma unroll
        for (int nt = 0; nt < 4; nt++) {
            int col = colBase + wn + nt * 8 + 2 * t;
            if (col < N) {
                float b0 = bias[col], b1 = bias[col + 1];
#pragma unroll
                for (int half = 0; half < 2; half++) {
                    int row = rowBase + wm + mt * 16 + g + half * 8;
                    float v0 = acc[mt][nt][half * 2 + 0] + b0;
                    float v1 = acc[mt][nt][half * 2 + 1] + b1;
                    if (EPI == 1) {
                        v0 += resid[(size_t)row * N + col];
                        v1 += resid[(size_t)row * N + col + 1];
                    }
                    if (EPI == 2) {
                        float u0 = v0, u1 = v1;
                        float t0 = 0.7978845608028654f * (u0 + 0.044715f * u0 * u0 * u0);
                        float t1 = 0.7978845608028654f * (u1 + 0.044715f * u1 * u1 * u1);
                        v0 = 0.5f * u0 * (1.f + tanhf(t0));
                        v1 = 0.5f * u1 * (1.f + tanhf(t1));
                    }
                    *(float2*)&C[(size_t)row * N + col] = make_float2(v0, v1);
                }
            }
        }
    }
}

// ---------------------------------------------------------------------------
// RoPE in place on q and k slices of g_qkv.
// ---------------------------------------------------------------------------
__global__ void rope_kernel(float* __restrict__ qkv,
                            const float* __restrict__ cosb,
                            const float* __restrict__ sinb)
{
    int idx = blockIdx.x * blockDim.x + threadIdx.x;
    const int total = SEQ * 2 * HEADS * 36;
    if (idx >= total) return;

    int d = idx % 36;   int t = idx / 36;
    int h = t % HEADS;  t /= HEADS;
    int part = t & 1;   int s = t >> 1;

    float c0  = cosb[s * HD + d];
    float sn0 = sinb[s * HD + d];
    float c1  = cosb[s * HD + d + 36];
    float sn1 = sinb[s * HD + d + 36];

    size_t base = (size_t)s * (3 * HID) + part * HID + h * HD;
    float v0 = qkv[base + d];
    float v1 = qkv[base + d + 36];
    qkv[base + d]      = v0 * c0 - v1 * sn0;
    qkv[base + d + 36] = v1 * c1 + v0 * sn1;
}

// ---------------------------------------------------------------------------
// Windowed attention: one block per (window, head). 128 threads.
// ---------------------------------------------------------------------------
__global__ __launch_bounds__(128) void attn_kernel(const float* __restrict__ qkv,
                                                   float* __restrict__ out)
{
    extern __shared__ float sm[];
    float* sq = sm;
    float* sk = sq + 64 * 73;
    float* sv = sk + 64 * 73;
    float* ss = sv + 64 * 73;

    int w   = blockIdx.x >> 4;
    int h   = blockIdx.x & 15;
    int tid = threadIdx.x;

    for (int i = tid; i < 64 * 72; i += 128) {
        int r = i / 72, d = i % 72;
        size_t base = (size_t)(w * 64 + r) * (3 * HID) + h * HD + d;
        sq[r * 73 + d] = qkv[base];
        sk[r * 73 + d] = qkv[base + HID];
        sv[r * 73 + d] = qkv[base + 2 * HID];
    }
    __syncthreads();

    const float scale = 0.11785113019775793f;
    int r    = tid >> 1;
    int half = tid & 1;

    for (int j = half * 32; j < half * 32 + 32; j++) {
        float a = 0.f;
#pragma unroll
        for (int d = 0; d < 72; d++) a += sq[r * 73 + d] * sk[j * 73 + d];
        ss[r * 65 + j] = a * scale;
    }
    __syncthreads();

    if (tid < 64) {
        float mx = -1e30f;
        for (int j = 0; j < 64; j++) mx = fmaxf(mx, ss[tid * 65 + j]);
        float sum = 0.f;
        for (int j = 0; j < 64; j++) {
            float e = __expf(ss[tid * 65 + j] - mx);
            ss[tid * 65 + j] = e;
            sum += e;
        }
        float inv = 1.f / sum;
        for (int j = 0; j < 64; j++) ss[tid * 65 + j] *= inv;
    }
    __syncthreads();

    {
        int dbase = half * 36;
        float acc[36] = {};
        for (int j = 0; j < 64; j++) {
            float p = ss[r * 65 + j];
#pragma unroll
            for (int d = 0; d < 36; d++) acc[d] += p * sv[j * 73 + dbase + d];
        }
        size_t obase = (size_t)(w * 64 + r) * HID + h * HD + dbase;
#pragma unroll
        for (int d = 0; d < 36; d++) out[obase + d] = acc[d];
    }
}

// ---------------------------------------------------------------------------
// Launch
// ---------------------------------------------------------------------------
extern "C" void kernel_launch(void* const* d_in, const int* in_sizes, int n_in,
                              void* d_out, int out_size)
{
    const float* x      = (const float*)d_in[0];
    const float* cosb   = (const float*)d_in[1];
    const float* sinb   = (const float*)d_in[2];
    const float* qkv_w  = (const float*)d_in[4];
    const float* qkv_b  = (const float*)d_in[5];
    const float* proj_w = (const float*)d_in[6];
    const float* proj_b = (const float*)d_in[7];
    const float* ln1_w  = (const float*)d_in[8];
    const float* ln1_b  = (const float*)d_in[9];
    const float* ln2_w  = (const float*)d_in[10];
    const float* ln2_b  = (const float*)d_in[11];
    const float* fc1_w  = (const float*)d_in[12];
    const float* fc1_b  = (const float*)d_in[13];
    const float* fc2_w  = (const float*)d_in[14];
    const float* fc2_b  = (const float*)d_in[15];
    float* out = (float*)d_out;

    float *ph, *pqkv, *pattn, *px1, *pm;
    cudaGetSymbolAddress((void**)&ph,    g_h);
    cudaGetSymbolAddress((void**)&pqkv,  g_qkv);
    cudaGetSymbolAddress((void**)&pattn, g_attn);
    cudaGetSymbolAddress((void**)&px1,   g_x1);
    cudaGetSymbolAddress((void**)&pm,    g_m);

    const int ATTN_SMEM = (64 * 73 * 3 + 64 * 65) * 4;
    cudaFuncSetAttribute(attn_kernel,
                         cudaFuncAttributeMaxDynamicSharedMemorySize, ATTN_SMEM);
    cudaFuncSetAttribute(gemm_tf32<0>,
                         cudaFuncAttributeMaxDynamicSharedMemorySize, GEMM_SMEM);
    cudaFuncSetAttribute(gemm_tf32<1>,
                         cudaFuncAttributeMaxDynamicSharedMemorySize, GEMM_SMEM);
    cudaFuncSetAttribute(gemm_tf32<2>,
                         cudaFuncAttributeMaxDynamicSharedMemorySize, GEMM_SMEM);

    // 1) LN1(x) -> h
    ln_kernel<<<SEQ / 8, 256>>>(x, ln1_w, ln1_b, ph);

    // 2) qkv = h @ qkv_w + qkv_b
    gemm_tf32<0><<<dim3(3 * HID / 128, SEQ / 128), 256, GEMM_SMEM>>>(
        ph, qkv_w, qkv_b, nullptr, pqkv, SEQ, 3 * HID, HID);

    // 3) RoPE in place on q, k
    {
        int n = SEQ * 2 * HEADS * 36;
        rope_kernel<<<(n + 255) / 256, 256>>>(pqkv, cosb, sinb);
    }

    // 4) windowed attention
    attn_kernel<<<NWIN * HEADS, 128, ATTN_SMEM>>>(pqkv, pattn);

    // 5) x1 = x + attn @ proj_w + proj_b
    gemm_tf32<1><<<dim3(HID / 128, SEQ / 128), 256, GEMM_SMEM>>>(
        pattn, proj_w, proj_b, x, px1, SEQ, HID, HID);

    // 6) LN2(x1) -> h
    ln_kernel<<<SEQ / 8, 256>>>(px1, ln2_w, ln2_b, ph);

    // 7) m = gelu(h @ fc1_w + fc1_b)
    gemm_tf32<2><<<dim3((INTER + 127) / 128, SEQ / 128), 256, GEMM_SMEM>>>(
        ph, fc1_w, fc1_b, nullptr, pm, SEQ, INTER, HID);

    // 8) out = x1 + m @ fc2_w + fc2_b
    gemm_tf32<1><<<dim3(HID / 128, SEQ / 128), 256, GEMM_SMEM>>>(
        pm, fc2_w, fc2_b, px1, out, SEQ, HID, INTER);
}

// round 9
// speedup vs baseline: 3.6969x; 1.1987x over previous
#include <cuda_runtime.h>
#include <math.h>
#include <stdint.h>

#define SEQ   16384
#define HID   1152
#define HEADS 16
#define HD    72
#define INTER 4304
#define NWIN  256

// ---------------------------------------------------------------------------
// Scratch (device globals; no runtime allocation allowed)
// ---------------------------------------------------------------------------
__device__ float g_h   [(size_t)SEQ * HID];
__device__ float g_qkv [(size_t)SEQ * 3 * HID];
__device__ float g_attn[(size_t)SEQ * HID];
__device__ float g_x1  [(size_t)SEQ * HID];
__device__ float g_m   [(size_t)SEQ * INTER];
// tf32-rounded weights (rounded once per launch)
__device__ float g_wqkv[(size_t)HID * 3 * HID];
__device__ float g_wproj[(size_t)HID * HID];
__device__ float g_wfc1[(size_t)HID * INTER];
__device__ float g_wfc2[(size_t)INTER * HID];

__device__ __forceinline__ float tf32r(float f)
{
    uint32_t u;
    asm("cvt.rna.tf32.f32 %0, %1;" : "=r"(u) : "f"(f));
    return __uint_as_float(u);
}

// ---------------------------------------------------------------------------
// Round a weight matrix to tf32 (vectorized, n % 4 == 0)
// ---------------------------------------------------------------------------
__global__ void round_w_kernel(const float* __restrict__ in,
                               float* __restrict__ out, int n4)
{
    int i = blockIdx.x * blockDim.x + threadIdx.x;
    if (i >= n4) return;
    float4 v = ((const float4*)in)[i];
    v.x = tf32r(v.x); v.y = tf32r(v.y); v.z = tf32r(v.z); v.w = tf32r(v.w);
    ((float4*)out)[i] = v;
}

// ---------------------------------------------------------------------------
// LayerNorm: one warp per row, output rounded to tf32 (feeds GEMM A)
// ---------------------------------------------------------------------------
__global__ void ln_kernel(const float* __restrict__ in,
                          const float* __restrict__ w,
                          const float* __restrict__ b,
                          float* __restrict__ out)
{
    int warp = (blockIdx.x * blockDim.x + threadIdx.x) >> 5;
    int lane = threadIdx.x & 31;
    if (warp >= SEQ) return;

    const float* row = in + (size_t)warp * HID;
    float v[36];
    float s = 0.f, s2 = 0.f;
#pragma unroll
    for (int i = 0; i < 36; i++) {
        v[i] = row[lane + 32 * i];
        s  += v[i];
        s2 += v[i] * v[i];
    }
#pragma unroll
    for (int o = 16; o > 0; o >>= 1) {
        s  += __shfl_xor_sync(0xFFFFFFFFu, s,  o);
        s2 += __shfl_xor_sync(0xFFFFFFFFu, s2, o);
    }
    float mean = s * (1.0f / HID);
    float var  = s2 * (1.0f / HID) - mean * mean;
    float rstd = rsqrtf(var + 1e-6f);

    float* orow = out + (size_t)warp * HID;
#pragma unroll
    for (int i = 0; i < 36; i++) {
        int c = lane + 32 * i;
        orow[c] = tf32r((v[i] - mean) * rstd * w[c] + b[c]);
    }
}

// ---------------------------------------------------------------------------
// tf32 tensor-core GEMM (inputs pre-rounded to tf32; no inner-loop cvt)
// 128x128x32 CTA tile, 256 threads, double-buffered cp.async.
// EPI: 0 = bias, 1 = bias + residual, 2 = bias + gelu (output tf32-rounded)
// ---------------------------------------------------------------------------
#define BM 128
#define BN 128
#define BK 32
#define ASTRIDE 36
#define BSTRIDE 136
#define A_TILE (BM * ASTRIDE)
#define B_TILE (BK * BSTRIDE)
#define GEMM_SMEM ((2 * A_TILE + 2 * B_TILE) * 4)

#define MMA_TF32(acc, a0, a1, a2, a3, b0, b1)                                  \
    asm volatile(                                                              \
        "mma.sync.aligned.m16n8k8.row.col.f32.tf32.tf32.f32 "                  \
        "{%0,%1,%2,%3}, {%4,%5,%6,%7}, {%8,%9}, {%0,%1,%2,%3};\n"              \
        : "+f"(acc[0]), "+f"(acc[1]), "+f"(acc[2]), "+f"(acc[3])               \
        : "r"(a0), "r"(a1), "r"(a2), "r"(a3), "r"(b0), "r"(b1))

template <int EPI>
__global__ __launch_bounds__(256) void gemm_tf32(
    const float* __restrict__ A, const float* __restrict__ B,
    const float* __restrict__ bias, const float* __restrict__ resid,
    float* __restrict__ C, int M, int N, int K)
{
    extern __shared__ float smf[];
    float* sA = smf;
    float* sB = smf + 2 * A_TILE;

    const int tid  = threadIdx.x;
    const int lane = tid & 31, warp = tid >> 5;
    const int g = lane >> 2, t = lane & 3;
    const int wm = (warp >> 2) * 64, wn = (warp & 3) * 32;
    const int rowBase = blockIdx.y * BM, colBase = blockIdx.x * BN;

    float acc[4][4][4];
#pragma unroll
    for (int i = 0; i < 4; i++)
#pragma unroll
        for (int j = 0; j < 4; j++)
#pragma unroll
            for (int c = 0; c < 4; c++) acc[i][j][c] = 0.f;

    const int nkt = (K + BK - 1) / BK;

    auto loadA = [&](int stage, int k0) {
#pragma unroll
        for (int i = 0; i < 4; i++) {
            int c  = tid + i * 256;
            int m  = c >> 3;
            int kc = (c & 7) * 4;
            int gk = k0 + kc;
            int sz = (gk < K) ? 16 : 0;
            const float* src = A + (size_t)(rowBase + m) * K + min(gk, K - 4);
            uint32_t dst = (uint32_t)__cvta_generic_to_shared(
                sA + stage * A_TILE + m * ASTRIDE + kc);
            asm volatile("cp.async.cg.shared.global [%0], [%1], 16, %2;\n"
                         :: "r"(dst), "l"(src), "r"(sz));
        }
    };
    auto loadB = [&](int stage, int k0) {
#pragma unroll
        for (int i = 0; i < 4; i++) {
            int c  = tid + i * 256;
            int kr = c >> 5;
            int nc = (c & 31) * 4;
            int gk = k0 + kr;
            int gn = colBase + nc;
            int sz = (gk < K && gn < N) ? 16 : 0;
            const float* src = B + (size_t)min(gk, K - 1) * N + min(gn, N - 4);
            uint32_t dst = (uint32_t)__cvta_generic_to_shared(
                sB + stage * B_TILE + kr * BSTRIDE + nc);
            asm volatile("cp.async.cg.shared.global [%0], [%1], 16, %2;\n"
                         :: "r"(dst), "l"(src), "r"(sz));
        }
    };

    loadA(0, 0);
    loadB(0, 0);
    asm volatile("cp.async.commit_group;\n");

    int stage = 0;
    for (int kt = 0; kt < nkt; kt++) {
        if (kt + 1 < nkt) {
            loadA(stage ^ 1, (kt + 1) * BK);
            loadB(stage ^ 1, (kt + 1) * BK);
            asm volatile("cp.async.commit_group;\n");
            asm volatile("cp.async.wait_group 1;\n");
        } else {
            asm volatile("cp.async.wait_group 0;\n");
        }
        __syncthreads();

        const float* a_s = sA + stage * A_TILE;
        const float* b_s = sB + stage * B_TILE;

#pragma unroll
        for (int ks = 0; ks < 4; ks++) {
            const int k8 = ks * 8;
            uint32_t af[4][4], bf[4][2];
#pragma unroll
            for (int mt = 0; mt < 4; mt++) {
                int r = wm + mt * 16 + g;
                af[mt][0] = __float_as_uint(a_s[(r    ) * ASTRIDE + k8 + t    ]);
                af[mt][1] = __float_as_uint(a_s[(r + 8) * ASTRIDE + k8 + t    ]);
                af[mt][2] = __float_as_uint(a_s[(r    ) * ASTRIDE + k8 + t + 4]);
                af[mt][3] = __float_as_uint(a_s[(r + 8) * ASTRIDE + k8 + t + 4]);
            }
#pragma unroll
            for (int nt = 0; nt < 4; nt++) {
                int cc = wn + nt * 8 + g;
                bf[nt][0] = __float_as_uint(b_s[(k8 + t    ) * BSTRIDE + cc]);
                bf[nt][1] = __float_as_uint(b_s[(k8 + t + 4) * BSTRIDE + cc]);
            }
#pragma unroll
            for (int mt = 0; mt < 4; mt++)
#pragma unroll
                for (int nt = 0; nt < 4; nt++)
                    MMA_TF32(acc[mt][nt], af[mt][0], af[mt][1], af[mt][2],
                             af[mt][3], bf[nt][0], bf[nt][1]);
        }
        __syncthreads();
        stage ^= 1;
    }

#pragma unroll
    for (int mt = 0; mt < 4; mt++) {
#pragma unroll
        for (int nt = 0; nt < 4; nt++) {
            int col = colBase + wn + nt * 8 + 2 * t;
            if (col < N) {
                float b0 = bias[col], b1 = bias[col + 1];
#pragma unroll
                for (int half = 0; half < 2; half++) {
                    int row = rowBase + wm + mt * 16 + g + half * 8;
                    float v0 = acc[mt][nt][half * 2 + 0] + b0;
                    float v1 = acc[mt][nt][half * 2 + 1] + b1;
                    if (EPI == 1) {
                        v0 += resid[(size_t)row * N + col];
                        v1 += resid[(size_t)row * N + col + 1];
                    }
                    if (EPI == 2) {
                        float u0 = v0, u1 = v1;
                        float t0 = 0.7978845608028654f * (u0 + 0.044715f * u0 * u0 * u0);
                        float t1 = 0.7978845608028654f * (u1 + 0.044715f * u1 * u1 * u1);
                        v0 = tf32r(0.5f * u0 * (1.f + tanhf(t0)));
                        v1 = tf32r(0.5f * u1 * (1.f + tanhf(t1)));
                    }
                    *(float2*)&C[(size_t)row * N + col] = make_float2(v0, v1);
                }
            }
        }
    }
}

// ---------------------------------------------------------------------------
// Windowed attention with tf32 MMA; RoPE fused into the loader.
// One block per (window, head), 128 threads (4 warps, each 16 query rows).
// smem: sq/sk/sv [64][76], ss [64][68]
// ---------------------------------------------------------------------------
#define QST 76
#define SST 68
#define ATTN_SMEM ((3 * 64 * QST + 64 * SST) * 4)

__global__ __launch_bounds__(128) void attn_kernel(const float* __restrict__ qkv,
                                                   const float* __restrict__ cosb,
                                                   const float* __restrict__ sinb,
                                                   float* __restrict__ out)
{
    extern __shared__ float sm[];
    float* sq = sm;
    float* sk = sq + 64 * QST;
    float* sv = sk + 64 * QST;
    float* ss = sv + 64 * QST;

    const int w   = blockIdx.x >> 4;
    const int h   = blockIdx.x & 15;
    const int tid = threadIdx.x;
    const float scale = 0.11785113019775793f;   // 72^-0.5

    // Load q,k (with RoPE; cos[d] == cos[d+36]) and v. All rounded to tf32.
    for (int p = tid; p < 64 * 36; p += 128) {
        int r = p / 36, d = p % 36;
        int tok = w * 64 + r;
        size_t base = (size_t)tok * (3 * HID) + h * HD;
        float c = cosb[tok * HD + d];
        float s = sinb[tok * HD + d];

        float q0 = qkv[base + d], q1 = qkv[base + d + 36];
        sq[r * QST + d]      = tf32r((q0 * c - q1 * s) * scale);
        sq[r * QST + d + 36] = tf32r((q1 * c + q0 * s) * scale);

        float k0 = qkv[base + HID + d], k1 = qkv[base + HID + d + 36];
        sk[r * QST + d]      = tf32r(k0 * c - k1 * s);
        sk[r * QST + d + 36] = tf32r(k1 * c + k0 * s);

        sv[r * QST + d]      = tf32r(qkv[base + 2 * HID + d]);
        sv[r * QST + d + 36] = tf32r(qkv[base + 2 * HID + d + 36]);
    }
    __syncthreads();

    const int lane = tid & 31, warp = tid >> 5;
    const int g = lane >> 2, t = lane & 3;
    const int rw = warp * 16;

    // ---- scores = Q @ K^T  (64x64x72, 9 k-steps) ----
    {
        float c1[8][4];
#pragma unroll
        for (int nt = 0; nt < 8; nt++)
#pragma unroll
            for (int c = 0; c < 4; c++) c1[nt][c] = 0.f;

#pragma unroll
        for (int ks = 0; ks < 9; ks++) {
            int k8 = ks * 8;
            uint32_t a0 = __float_as_uint(sq[(rw + g    ) * QST + k8 + t    ]);
            uint32_t a1 = __float_as_uint(sq[(rw + g + 8) * QST + k8 + t    ]);
            uint32_t a2 = __float_as_uint(sq[(rw + g    ) * QST + k8 + t + 4]);
            uint32_t a3 = __float_as_uint(sq[(rw + g + 8) * QST + k8 + t + 4]);
#pragma unroll
            for (int nt = 0; nt < 8; nt++) {
                uint32_t b0 = __float_as_uint(sk[(nt * 8 + g) * QST + k8 + t    ]);
                uint32_t b1 = __float_as_uint(sk[(nt * 8 + g) * QST + k8 + t + 4]);
                MMA_TF32(c1[nt], a0, a1, a2, a3, b0, b1);
            }
        }
#pragma unroll
        for (int nt = 0; nt < 8; nt++) {
            *(float2*)&ss[(rw + g    ) * SST + nt * 8 + 2 * t] =
                make_float2(c1[nt][0], c1[nt][1]);
            *(float2*)&ss[(rw + g + 8) * SST + nt * 8 + 2 * t] =
                make_float2(c1[nt][2], c1[nt][3]);
        }
    }
    __syncthreads();

    // ---- softmax (2 threads per row, shfl pair-reduce) ----
    {
        int r = tid >> 1, hf = tid & 1;
        float* row = ss + r * SST + hf * 32;
        float mx = -1e30f;
#pragma unroll
        for (int j = 0; j < 32; j++) mx = fmaxf(mx, row[j]);
        mx = fmaxf(mx, __shfl_xor_sync(0xFFFFFFFFu, mx, 1));
        float e[32], sum = 0.f;
#pragma unroll
        for (int j = 0; j < 32; j++) { e[j] = __expf(row[j] - mx); sum += e[j]; }
        sum += __shfl_xor_sync(0xFFFFFFFFu, sum, 1);
        float inv = 1.f / sum;
#pragma unroll
        for (int j = 0; j < 32; j++) row[j] = tf32r(e[j] * inv);
    }
    __syncthreads();

    // ---- out = P @ V  (64x72x64, 8 k-steps, 9 n-tiles) ----
    {
        float c2[9][4];
#pragma unroll
        for (int nt = 0; nt < 9; nt++)
#pragma unroll
            for (int c = 0; c < 4; c++) c2[nt][c] = 0.f;

#pragma unroll
        for (int ks = 0; ks < 8; ks++) {
            int k8 = ks * 8;
            uint32_t a0 = __float_as_uint(ss[(rw + g    ) * SST + k8 + t    ]);
            uint32_t a1 = __float_as_uint(ss[(rw + g + 8) * SST + k8 + t    ]);
            uint32_t a2 = __float_as_uint(ss[(rw + g    ) * SST + k8 + t + 4]);
            uint32_t a3 = __float_as_uint(ss[(rw + g + 8) * SST + k8 + t + 4]);
#pragma unroll
            for (int nt = 0; nt < 9; nt++) {
                uint32_t b0 = __float_as_uint(sv[(k8 + t    ) * QST + nt * 8 + g]);
                uint32_t b1 = __float_as_uint(sv[(k8 + t + 4) * QST + nt * 8 + g]);
                MMA_TF32(c2[nt], a0, a1, a2, a3, b0, b1);
            }
        }

        // write rounded to tf32 (feeds proj GEMM as A)
#pragma unroll
        for (int nt = 0; nt < 9; nt++) {
            size_t o0 = (size_t)(w * 64 + rw + g) * HID + h * HD + nt * 8 + 2 * t;
            size_t o1 = o0 + (size_t)8 * HID;
            *(float2*)&out[o0] = make_float2(tf32r(c2[nt][0]), tf32r(c2[nt][1]));
            *(float2*)&out[o1] = make_float2(tf32r(c2[nt][2]), tf32r(c2[nt][3]));
        }
    }
}

// ---------------------------------------------------------------------------
// Launch
// ---------------------------------------------------------------------------
extern "C" void kernel_launch(void* const* d_in, const int* in_sizes, int n_in,
                              void* d_out, int out_size)
{
    const float* x      = (const float*)d_in[0];
    const float* cosb   = (const float*)d_in[1];
    const float* sinb   = (const float*)d_in[2];
    const float* qkv_w  = (const float*)d_in[4];
    const float* qkv_b  = (const float*)d_in[5];
    const float* proj_w = (const float*)d_in[6];
    const float* proj_b = (const float*)d_in[7];
    const float* ln1_w  = (const float*)d_in[8];
    const float* ln1_b  = (const float*)d_in[9];
    const float* ln2_w  = (const float*)d_in[10];
    const float* ln2_b  = (const float*)d_in[11];
    const float* fc1_w  = (const float*)d_in[12];
    const float* fc1_b  = (const float*)d_in[13];
    const float* fc2_w  = (const float*)d_in[14];
    const float* fc2_b  = (const float*)d_in[15];
    float* out = (float*)d_out;

    float *ph, *pqkv, *pattn, *px1, *pm, *pwqkv, *pwproj, *pwfc1, *pwfc2;
    cudaGetSymbolAddress((void**)&ph,     g_h);
    cudaGetSymbolAddress((void**)&pqkv,   g_qkv);
    cudaGetSymbolAddress((void**)&pattn,  g_attn);
    cudaGetSymbolAddress((void**)&px1,    g_x1);
    cudaGetSymbolAddress((void**)&pm,     g_m);
    cudaGetSymbolAddress((void**)&pwqkv,  g_wqkv);
    cudaGetSymbolAddress((void**)&pwproj, g_wproj);
    cudaGetSymbolAddress((void**)&pwfc1,  g_wfc1);
    cudaGetSymbolAddress((void**)&pwfc2,  g_wfc2);

    cudaFuncSetAttribute(attn_kernel,
                         cudaFuncAttributeMaxDynamicSharedMemorySize, ATTN_SMEM);
    cudaFuncSetAttribute(gemm_tf32<0>,
                         cudaFuncAttributeMaxDynamicSharedMemorySize, GEMM_SMEM);
    cudaFuncSetAttribute(gemm_tf32<1>,
                         cudaFuncAttributeMaxDynamicSharedMemorySize, GEMM_SMEM);
    cudaFuncSetAttribute(gemm_tf32<2>,
                         cudaFuncAttributeMaxDynamicSharedMemorySize, GEMM_SMEM);

    // 0) round weights to tf32
    {
        int n;
        n = HID * 3 * HID / 4;
        round_w_kernel<<<(n + 255) / 256, 256>>>(qkv_w,  pwqkv,  n);
        n = HID * HID / 4;
        round_w_kernel<<<(n + 255) / 256, 256>>>(proj_w, pwproj, n);
        n = HID * INTER / 4;
        round_w_kernel<<<(n + 255) / 256, 256>>>(fc1_w,  pwfc1,  n);
        n = INTER * HID / 4;
        round_w_kernel<<<(n + 255) / 256, 256>>>(fc2_w,  pwfc2,  n);
    }

    // 1) LN1(x) -> h (tf32-rounded)
    ln_kernel<<<SEQ / 8, 256>>>(x, ln1_w, ln1_b, ph);

    // 2) qkv = h @ qkv_w + qkv_b
    gemm_tf32<0><<<dim3(3 * HID / 128, SEQ / 128), 256, GEMM_SMEM>>>(
        ph, pwqkv, qkv_b, nullptr, pqkv, SEQ, 3 * HID, HID);

    // 3) windowed attention (RoPE fused)
    attn_kernel<<<NWIN * HEADS, 128, ATTN_SMEM>>>(pqkv, cosb, sinb, pattn);

    // 4) x1 = x + attn @ proj_w + proj_b
    gemm_tf32<1><<<dim3(HID / 128, SEQ / 128), 256, GEMM_SMEM>>>(
        pattn, pwproj, proj_b, x, px1, SEQ, HID, HID);

    // 5) LN2(x1) -> h (tf32-rounded)
    ln_kernel<<<SEQ / 8, 256>>>(px1, ln2_w, ln2_b, ph);

    // 6) m = gelu(h @ fc1_w + fc1_b) (tf32-rounded)
    gemm_tf32<2><<<dim3((INTER + 127) / 128, SEQ / 128), 256, GEMM_SMEM>>>(
        ph, pwfc1, fc1_b, nullptr, pm, SEQ, INTER, HID);

    // 7) out = x1 + m @ fc2_w + fc2_b
    gemm_tf32<1><<<dim3(HID / 128, SEQ / 128), 256, GEMM_SMEM>>>(
        pm, pwfc2, fc2_b, px1, out, SEQ, HID, INTER);
}